// round 16
// baseline (speedup 1.0000x reference)
#include <cuda_runtime.h>
#include <cstdint>

// SobelEdge3D: out = sqrt(ed^2 + eh^2 + ew^2 + 1e-6), separable Sobel.
// Round-16: R15 with ring depth 6 (prefetch distance 5 planes ~= 1700 cyc)
// to cover loaded-DRAM latency. Otherwise identical: shared plane tile
// (10 halo rows), cp.async.cg staging, st.global.cs output, one
// __syncthreads per plane, h-first separable math.
// Thread = 4 w (float4) x 2 h rows x 16 d outputs.

constexpr int Wd  = 128;
constexpr int Hd  = 128;
constexpr int Dd  = 64;
constexpr int BCn = 32;          // B*C = 2*16
constexpr int HT  = 8;           // output h rows per block
constexpr int ND  = 16;          // d outputs per block
constexpr int HW  = Hd * Wd;
constexpr int NSLOT = 6;         // ring depth (planes in flight: 5)
constexpr int SROWS = HT + 2;    // 10 tile rows: h0-1 .. h0+8
constexpr int NPL   = ND + 2;    // 18 planes consumed per block

__device__ __forceinline__ float sqrt_approx(float v) {
    float r; asm("sqrt.approx.f32 %0,%1;" : "=f"(r) : "f"(v)); return r;
}
__device__ __forceinline__ void cp16(uint32_t dst, const float* src, int sz) {
    // 16B async copy, L1-bypass (.cg); sz=0 => zero-fill (padding).
    asm volatile("cp.async.cg.shared.global [%0], [%1], 16, %2;"
                 :: "r"(dst), "l"(src), "r"(sz));
}
__device__ __forceinline__ void cp_commit() {
    asm volatile("cp.async.commit_group;" ::: "memory");
}
__device__ __forceinline__ void cp_wait4() {
    asm volatile("cp.async.wait_group 4;" ::: "memory");
}
__device__ __forceinline__ void stcs128(float* p, float4 v) {
    asm volatile("st.global.cs.v4.f32 [%0], {%1,%2,%3,%4};"
                 :: "l"(p), "f"(v.x), "f"(v.y), "f"(v.z), "f"(v.w) : "memory");
}

__global__ __launch_bounds__(128, 5)
void sobel3d_kernel(const float* __restrict__ x, float* __restrict__ out)
{
    // Shared plane ring: plane k lives in slot k % 6. 6 x 10 x 128 f32 = 30 KB.
    __shared__ alignas(16) float tile[NSLOT][SROWS][Wd];

    const int tid = threadIdx.x;
    const int tx  = tid & 31;                 // w = 4*tx .. 4*tx+3
    const int ty  = tid >> 5;                 // 0..3
    const int h0  = blockIdx.x * HT;
    const int d0  = blockIdx.y * ND;

    const float* __restrict__ xb = x   + (size_t)blockIdx.z * (Dd * HW);
    float* __restrict__       ob = out + (size_t)blockIdx.z * (Dd * HW);

    const uint32_t tb = (uint32_t)__cvta_generic_to_shared(tile);

    // Produce plane k (= d-index d0-1+k) into slot k%6.
    // Thread tid writes rows ty+4j (j=0,1[,2 if ty<2]) at column tx (16B).
    auto cp_plane = [&](int k) {
        if (k >= NPL) { cp_commit(); return; }     // tail: empty group
        const int p  = d0 - 1 + k;
        const int pc = min(max(p, 0), Dd - 1);     // clamped address (safety)
        const bool pv = (unsigned)p < (unsigned)Dd;
        const float* pb = xb + pc * HW + (tx << 2);
        const uint32_t db = tb + (k % NSLOT) * (SROWS * Wd * 4) + (tx << 4);
        #pragma unroll
        for (int j = 0; j < 3; ++j) {
            const int r = ty + 4 * j;              // tile row
            if (r < SROWS) {
                const int hh = h0 - 1 + r;         // global h of tile row r
                const int hc = min(max(hh, 0), Hd - 1);
                const int sz = (pv && (unsigned)hh < (unsigned)Hd) ? 16 : 0;
                cp16(db + r * (Wd * 4), pb + hc * Wd, sz);
            }
        }
        cp_commit();
    };

    // Consume plane k: wait, block-sync, read 4 rows, h-first fold to A/B/C.
    auto abc = [&](int k, float (&A)[2][4], float (&B)[2][4], float (&C)[2][4]) {
        cp_wait4();
        __syncthreads();
        const int s = k % NSLOT;
        float q[4][4];
        #pragma unroll
        for (int r = 0; r < 4; ++r) {
            // tile row (2ty + r) = global h row h0+2ty-1+r (pads already zeroed)
            float4 v = *(const float4*)&tile[s][(ty << 1) + r][tx << 2];
            q[r][0] = v.x; q[r][1] = v.y; q[r][2] = v.z; q[r][3] = v.w;
        }
        // h-stage: hs[o] = s_h, hg[o] = g_h for output rows o=0,1.
        float hs[2][4], hg[2][4];
        #pragma unroll
        for (int j = 0; j < 4; ++j) {
            hs[0][j] = fmaf(2.f, q[1][j], q[0][j] + q[2][j]);
            hg[0][j] = q[2][j] - q[0][j];
            hs[1][j] = fmaf(2.f, q[2][j], q[1][j] + q[3][j]);
            hg[1][j] = q[3][j] - q[1][j];
        }
        // w-stage: A = g_w(hs), B = s_w(hg), C = s_w(hs).
        #pragma unroll
        for (int o = 0; o < 2; ++o) {
            float lfs = __shfl_up_sync(0xffffffffu, hs[o][3], 1);
            float rts = __shfl_down_sync(0xffffffffu, hs[o][0], 1);
            float lfg = __shfl_up_sync(0xffffffffu, hg[o][3], 1);
            float rtg = __shfl_down_sync(0xffffffffu, hg[o][0], 1);
            if (tx == 0)  { lfs = 0.f; lfg = 0.f; }   // zero pad w = -1
            if (tx == 31) { rts = 0.f; rtg = 0.f; }   // zero pad w = 128
            A[o][0] = hs[o][1] - lfs;
            A[o][1] = hs[o][2] - hs[o][0];
            A[o][2] = hs[o][3] - hs[o][1];
            A[o][3] = rts      - hs[o][2];
            B[o][0] = fmaf(2.f, hg[o][0], lfg      + hg[o][1]);
            B[o][1] = fmaf(2.f, hg[o][1], hg[o][0] + hg[o][2]);
            B[o][2] = fmaf(2.f, hg[o][2], hg[o][1] + hg[o][3]);
            B[o][3] = fmaf(2.f, hg[o][3], hg[o][2] + rtg);
            C[o][0] = fmaf(2.f, hs[o][0], lfs      + hs[o][1]);
            C[o][1] = fmaf(2.f, hs[o][1], hs[o][0] + hs[o][2]);
            C[o][2] = fmaf(2.f, hs[o][2], hs[o][1] + hs[o][3]);
            C[o][3] = fmaf(2.f, hs[o][3], hs[o][2] + rts);
        }
    };

    float a[2][4], b[2][4], c[2][4];
    float ed0[2][4], eh0[2][4], ed1[2][4], eh1[2][4], Cp[2][4], Cq[2][4];

    // Prologue: planes k = 0..4 in flight (prefetch distance 5).
    cp_plane(0); cp_plane(1); cp_plane(2); cp_plane(3); cp_plane(4);

    // Consume k=0 (plane d0-1); refill k=5.
    abc(0, a, b, c);
    #pragma unroll
    for (int o = 0; o < 2; ++o)
        #pragma unroll
        for (int j = 0; j < 4; ++j) {
            ed0[o][j] = a[o][j]; eh0[o][j] = b[o][j]; Cp[o][j] = c[o][j];
        }
    cp_plane(5);

    // Consume k=1 (plane d0); refill k=6.
    abc(1, a, b, c);
    #pragma unroll
    for (int o = 0; o < 2; ++o)
        #pragma unroll
        for (int j = 0; j < 4; ++j) {
            ed0[o][j] = fmaf(2.f, a[o][j], ed0[o][j]);
            eh0[o][j] = fmaf(2.f, b[o][j], eh0[o][j]);
            ed1[o][j] = a[o][j]; eh1[o][j] = b[o][j]; Cq[o][j] = c[o][j];
        }
    cp_plane(6);

    const int obase = d0 * HW + (h0 + (ty << 1)) * Wd + (tx << 2);

    // Steady state: iter i consumes k=i+2 (plane d0+1+i), refills k=i+7.
    #pragma unroll
    for (int i = 0; i < ND; ++i) {
        abc(i + 2, a, b, c);

        #pragma unroll
        for (int o = 0; o < 2; ++o) {
            float res[4];
            #pragma unroll
            for (int j = 0; j < 4; ++j) {
                float ed = ed0[o][j] + a[o][j];
                float eh = eh0[o][j] + b[o][j];
                float ew = c[o][j] - Cp[o][j];
                float m  = fmaf(ew, ew, fmaf(eh, eh, fmaf(ed, ed, 1e-6f)));
                res[j] = sqrt_approx(m);
                ed0[o][j] = fmaf(2.f, a[o][j], ed1[o][j]);
                eh0[o][j] = fmaf(2.f, b[o][j], eh1[o][j]);
                ed1[o][j] = a[o][j];
                eh1[o][j] = b[o][j];
                Cp[o][j]  = Cq[o][j];
                Cq[o][j]  = c[o][j];
            }
            stcs128(ob + obase + i * HW + o * Wd,
                    make_float4(res[0], res[1], res[2], res[3]));
        }
        cp_plane(i + 7);            // empty group past the last needed plane
    }
}

extern "C" void kernel_launch(void* const* d_in, const int* in_sizes, int n_in,
                              void* d_out, int out_size)
{
    const float* x = (const float*)d_in[0];
    float* out = (float*)d_out;
    dim3 grid(Hd / HT, Dd / ND, BCn);   // (16, 4, 32) = 2048 blocks
    dim3 block(128);                    // 4 warps; thread = 4w x 2h x 16d
    sobel3d_kernel<<<grid, block>>>(x, out);
}

// round 17
// speedup vs baseline: 1.0059x; 1.0059x over previous
#include <cuda_runtime.h>
#include <cstdint>

// SobelEdge3D: out = sqrt(ed^2 + eh^2 + ew^2 + 1e-6), separable Sobel.
// Round-17: R16's pipeline (shared plane tile, cp.async.cg depth-6 ring,
// st.cs output, h-first math) reshaped to 256-thread blocks with ONE h-row
// per thread: same 16 FP/elem as the 2-row shape but ~60 regs -> 4 CTAs x
// 8 warps = 32 warps/SM (+60% latency cover).
// Thread = 4 w (float4) x 1 h row x 16 d outputs.

constexpr int Wd  = 128;
constexpr int Hd  = 128;
constexpr int Dd  = 64;
constexpr int BCn = 32;          // B*C = 2*16
constexpr int HT  = 8;           // output h rows per block (1 per warp)
constexpr int ND  = 16;          // d outputs per block
constexpr int HW  = Hd * Wd;
constexpr int NSLOT = 6;         // ring depth (5 planes in flight)
constexpr int SROWS = HT + 2;    // 10 tile rows: h0-1 .. h0+8
constexpr int NPL   = ND + 2;    // 18 planes consumed per block

__device__ __forceinline__ float sqrt_approx(float v) {
    float r; asm("sqrt.approx.f32 %0,%1;" : "=f"(r) : "f"(v)); return r;
}
__device__ __forceinline__ void cp16(uint32_t dst, const float* src, int sz) {
    // 16B async copy, L1-bypass (.cg); sz=0 => zero-fill (padding).
    asm volatile("cp.async.cg.shared.global [%0], [%1], 16, %2;"
                 :: "r"(dst), "l"(src), "r"(sz));
}
__device__ __forceinline__ void cp_commit() {
    asm volatile("cp.async.commit_group;" ::: "memory");
}
__device__ __forceinline__ void cp_wait4() {
    asm volatile("cp.async.wait_group 4;" ::: "memory");
}
__device__ __forceinline__ void stcs128(float* p, float4 v) {
    asm volatile("st.global.cs.v4.f32 [%0], {%1,%2,%3,%4};"
                 :: "l"(p), "f"(v.x), "f"(v.y), "f"(v.z), "f"(v.w) : "memory");
}

__global__ __launch_bounds__(256, 4)
void sobel3d_kernel(const float* __restrict__ x, float* __restrict__ out)
{
    // Shared plane ring: plane k in slot k % 6. 6 x 10 x 128 f32 = 30 KB.
    __shared__ alignas(16) float tile[NSLOT][SROWS][Wd];

    const int tid = threadIdx.x;
    const int tx  = tid & 31;                 // w = 4*tx .. 4*tx+3
    const int wy  = tid >> 5;                 // 0..7 -> output h row h0+wy
    const int h0  = blockIdx.x * HT;
    const int d0  = blockIdx.y * ND;

    const float* __restrict__ xb = x   + (size_t)blockIdx.z * (Dd * HW);
    float* __restrict__       ob = out + (size_t)blockIdx.z * (Dd * HW);

    const uint32_t tb = (uint32_t)__cvta_generic_to_shared(tile) + (tx << 4);

    // Producer partition (320 segs over 256 threads): thread covers tile row
    // wy at col tx, plus (for wy<2) tile row wy+8 at col tx. Hoisted.
    int roff0, rsz0, roff1 = 0, rsz1 = 0;
    uint32_t soff0, soff1 = 0;
    {
        const int hh0 = h0 - 1 + wy;
        roff0 = min(max(hh0, 0), Hd - 1) * Wd + (tx << 2);
        rsz0  = ((unsigned)hh0 < (unsigned)Hd) ? 16 : 0;
        soff0 = wy * (Wd * 4);
        if (wy < 2) {
            const int hh1 = h0 + 7 + wy;          // tile row wy+8
            roff1 = min(max(hh1, 0), Hd - 1) * Wd + (tx << 2);
            rsz1  = ((unsigned)hh1 < (unsigned)Hd) ? 16 : 0;
            soff1 = (wy + 8) * (Wd * 4);
        }
    }

    // Produce plane k (= d-index d0-1+k) into slot k%6; always commits.
    auto cp_plane = [&](int k) {
        if (k >= NPL) { cp_commit(); return; }    // tail: empty group
        const int p  = d0 - 1 + k;
        const int pc = min(max(p, 0), Dd - 1);    // clamped (addr safety)
        const int pv = ((unsigned)p < (unsigned)Dd) ? 16 : 0;
        const float* pb = xb + pc * HW;
        const uint32_t db = tb + (k % NSLOT) * (SROWS * Wd * 4);
        cp16(db + soff0, pb + roff0, min(rsz0, pv));
        if (wy < 2)
            cp16(db + soff1, pb + roff1, min(rsz1, pv));
        cp_commit();
    };

    // Consume plane k: wait, block-sync, read rows wy..wy+2, h-first A/B/C.
    auto abc = [&](int k, float (&A)[4], float (&B)[4], float (&C)[4]) {
        cp_wait4();
        __syncthreads();
        const int s = k % NSLOT;
        float q[3][4];
        #pragma unroll
        for (int r = 0; r < 3; ++r) {
            // tile row (wy + r) = global h row h0+wy-1+r (pads are zeroed)
            float4 v = *(const float4*)&tile[s][wy + r][tx << 2];
            q[r][0] = v.x; q[r][1] = v.y; q[r][2] = v.z; q[r][3] = v.w;
        }
        // h-stage: hs = s_h(x), hg = g_h(x).
        float hs[4], hg[4];
        #pragma unroll
        for (int j = 0; j < 4; ++j) {
            hs[j] = fmaf(2.f, q[1][j], q[0][j] + q[2][j]);
            hg[j] = q[2][j] - q[0][j];
        }
        // w-stage: A = g_w(hs), B = s_w(hg), C = s_w(hs).
        float lfs = __shfl_up_sync(0xffffffffu, hs[3], 1);
        float rts = __shfl_down_sync(0xffffffffu, hs[0], 1);
        float lfg = __shfl_up_sync(0xffffffffu, hg[3], 1);
        float rtg = __shfl_down_sync(0xffffffffu, hg[0], 1);
        if (tx == 0)  { lfs = 0.f; lfg = 0.f; }   // zero pad w = -1
        if (tx == 31) { rts = 0.f; rtg = 0.f; }   // zero pad w = 128
        A[0] = hs[1] - lfs;
        A[1] = hs[2] - hs[0];
        A[2] = hs[3] - hs[1];
        A[3] = rts   - hs[2];
        B[0] = fmaf(2.f, hg[0], lfg   + hg[1]);
        B[1] = fmaf(2.f, hg[1], hg[0] + hg[2]);
        B[2] = fmaf(2.f, hg[2], hg[1] + hg[3]);
        B[3] = fmaf(2.f, hg[3], hg[2] + rtg);
        C[0] = fmaf(2.f, hs[0], lfs   + hs[1]);
        C[1] = fmaf(2.f, hs[1], hs[0] + hs[2]);
        C[2] = fmaf(2.f, hs[2], hs[1] + hs[3]);
        C[3] = fmaf(2.f, hs[3], hs[2] + rts);
    };

    float a[4], b[4], c[4];
    float ed0[4], eh0[4], ed1[4], eh1[4], Cp[4], Cq[4];

    // Prologue: planes k = 0..4 in flight (prefetch distance 5).
    cp_plane(0); cp_plane(1); cp_plane(2); cp_plane(3); cp_plane(4);

    // Consume k=0 (plane d0-1); refill k=5.
    abc(0, a, b, c);
    #pragma unroll
    for (int j = 0; j < 4; ++j) {
        ed0[j] = a[j]; eh0[j] = b[j]; Cp[j] = c[j];
    }
    cp_plane(5);

    // Consume k=1 (plane d0); refill k=6.
    abc(1, a, b, c);
    #pragma unroll
    for (int j = 0; j < 4; ++j) {
        ed0[j] = fmaf(2.f, a[j], ed0[j]);
        eh0[j] = fmaf(2.f, b[j], eh0[j]);
        ed1[j] = a[j]; eh1[j] = b[j]; Cq[j] = c[j];
    }
    cp_plane(6);

    const int obase = d0 * HW + (h0 + wy) * Wd + (tx << 2);

    // Steady state: iter i consumes k=i+2 (plane d0+1+i), refills k=i+7.
    #pragma unroll
    for (int i = 0; i < ND; ++i) {
        abc(i + 2, a, b, c);

        float res[4];
        #pragma unroll
        for (int j = 0; j < 4; ++j) {
            float ed = ed0[j] + a[j];
            float eh = eh0[j] + b[j];
            float ew = c[j] - Cp[j];
            float m  = fmaf(ew, ew, fmaf(eh, eh, fmaf(ed, ed, 1e-6f)));
            res[j] = sqrt_approx(m);
            ed0[j] = fmaf(2.f, a[j], ed1[j]);
            eh0[j] = fmaf(2.f, b[j], eh1[j]);
            ed1[j] = a[j];
            eh1[j] = b[j];
            Cp[j]  = Cq[j];
            Cq[j]  = c[j];
        }
        stcs128(ob + obase + i * HW,
                make_float4(res[0], res[1], res[2], res[3]));

        cp_plane(i + 7);            // empty group past the last needed plane
    }
}

extern "C" void kernel_launch(void* const* d_in, const int* in_sizes, int n_in,
                              void* d_out, int out_size)
{
    const float* x = (const float*)d_in[0];
    float* out = (float*)d_out;
    dim3 grid(Hd / HT, Dd / ND, BCn);   // (16, 4, 32) = 2048 blocks
    dim3 block(256);                    // 8 warps; thread = 4w x 1h x 16d
    sobel3d_kernel<<<grid, block>>>(x, out);
}